// round 2
// baseline (speedup 1.0000x reference)
#include <cuda_runtime.h>
#include <stdint.h>

#define BB 4
#define IC 64
#define OCC 64
#define HH 32
#define WW 32
#define HP 34
#define WP 34
#define NPIX (BB*OCC*HH*WW)   // 262144
#define IC_CHUNK 4

// ---------------- scratch (device globals: no allocation allowed) ----------------
__device__ float4 d_wpack[OCC*IC*9];          // {w, 2w, 4w^2, 8w^3}
__device__ float  d_w4[OCC*IC*9];             // 16 w^4
__device__ float4 d_inpack[BB*IC*HP*WP];      // padded {x, q, x*q, 0}

// ---------------- threefry-2x32-20, key = (0, 42) ----------------
__device__ __forceinline__ unsigned rotl32(unsigned v, int s){ return (v<<s)|(v>>(32-s)); }

__device__ __forceinline__ void threefry_0_42(unsigned x0, unsigned x1, unsigned &o0, unsigned &o1){
  const unsigned k0 = 0u, k1 = 42u, k2 = 0u ^ 42u ^ 0x1BD11BDAu;
  x0 += k0; x1 += k1;
  // group 0: rotations {13,15,26,6}
  x0+=x1; x1=rotl32(x1,13); x1^=x0;
  x0+=x1; x1=rotl32(x1,15); x1^=x0;
  x0+=x1; x1=rotl32(x1,26); x1^=x0;
  x0+=x1; x1=rotl32(x1, 6); x1^=x0;
  x0+=k1; x1+=k2+1u;
  // group 1: {17,29,16,24}
  x0+=x1; x1=rotl32(x1,17); x1^=x0;
  x0+=x1; x1=rotl32(x1,29); x1^=x0;
  x0+=x1; x1=rotl32(x1,16); x1^=x0;
  x0+=x1; x1=rotl32(x1,24); x1^=x0;
  x0+=k2; x1+=k0+2u;
  // group 2
  x0+=x1; x1=rotl32(x1,13); x1^=x0;
  x0+=x1; x1=rotl32(x1,15); x1^=x0;
  x0+=x1; x1=rotl32(x1,26); x1^=x0;
  x0+=x1; x1=rotl32(x1, 6); x1^=x0;
  x0+=k0; x1+=k1+3u;
  // group 3
  x0+=x1; x1=rotl32(x1,17); x1^=x0;
  x0+=x1; x1=rotl32(x1,29); x1^=x0;
  x0+=x1; x1=rotl32(x1,16); x1^=x0;
  x0+=x1; x1=rotl32(x1,24); x1^=x0;
  x0+=k1; x1+=k2+4u;
  // group 4
  x0+=x1; x1=rotl32(x1,13); x1^=x0;
  x0+=x1; x1=rotl32(x1,15); x1^=x0;
  x0+=x1; x1=rotl32(x1,26); x1^=x0;
  x0+=x1; x1=rotl32(x1, 6); x1^=x0;
  x0+=k2; x1+=k0+5u;
  o0 = x0; o1 = x1;
}

// JAX partitionable threefry (default since 0.4.30):
// per-element 64-bit counter i -> (hi, lo) = (0, i); bits32 = o0 ^ o1.
// uniform = bitcast((bits>>9)|0x3f800000) - 1
__device__ __forceinline__ float jax_uniform(unsigned idx){
  unsigned r0, r1;
  threefry_0_42(0u, idx, r0, r1);
  unsigned bits = r0 ^ r1;
  return __uint_as_float((bits >> 9) | 0x3f800000u) - 1.0f;
}

// ---------------- prep kernels ----------------
__global__ void prep_weights(const float* __restrict__ weight){
  int i = blockIdx.x*blockDim.x + threadIdx.x;
  if (i >= OCC*IC*9) return;
  float w  = weight[i];
  float w2 = w*w;
  d_wpack[i] = make_float4(w, 2.f*w, 4.f*w2, 8.f*w2*w);
  d_w4[i]    = 16.f*w2*w2;
}

__global__ void prep_inputs(const float* __restrict__ x, const float* __restrict__ q){
  int i = blockIdx.x*blockDim.x + threadIdx.x;
  if (i >= BB*IC*HP*WP) return;
  int xw = i % WP; int t = i / WP;
  int yh = t % HP; int bc = t / HP;   // bc = b*IC + ic
  float4 v = make_float4(0.f, 0.f, 0.f, 0.f);
  if (xw >= 1 && xw <= WW && yh >= 1 && yh <= HH){
    int src = (bc*HH + (yh-1))*WW + (xw-1);
    float xv = x[src], qv = q[src];
    v = make_float4(xv, qv, xv*qv, 0.f);
  }
  d_inpack[i] = v;
}

// ---------------- fused main kernel ----------------
// block: 32x8 threads = one 32x8 output tile for one (b, oc).
// grid: (H/8, OC, B)
__global__ void __launch_bounds__(256)
sbc_main(const float* __restrict__ bias, float* __restrict__ out){
  __shared__ float4 s_w [IC*9];
  __shared__ float  s_w4[IC*9];
  __shared__ float4 s_in[IC_CHUNK][10][WP];

  const int ty = blockIdx.x;     // row tile 0..3
  const int oc = blockIdx.y;
  const int b  = blockIdx.z;
  const int rx = threadIdx.x;    // 0..31 (output col)
  const int ry = threadIdx.y;    // 0..7  (output row in tile)
  const int tid = ry*32 + rx;

  // weights for this oc
  for (int i = tid; i < IC*9; i += 256){
    s_w [i] = d_wpack[oc*IC*9 + i];
    s_w4[i] = d_w4  [oc*IC*9 + i];
  }

  float a0=0.f, s1=0.f, s2=0.f, s3=0.f, s4=0.f;
  const int rowbase = ty*8;

  for (int cc = 0; cc < IC/IC_CHUNK; cc++){
    __syncthreads();
    // load padded input chunk: IC_CHUNK x 10 rows x 34 cols
    for (int i = tid; i < IC_CHUNK*10*WP; i += 256){
      int lx = i % WP; int t = i / WP;
      int ly = t % 10; int icl = t / 10;
      s_in[icl][ly][lx] =
        d_inpack[((b*IC + cc*IC_CHUNK + icl)*HP + rowbase + ly)*WP + lx];
    }
    __syncthreads();

    #pragma unroll
    for (int icl = 0; icl < IC_CHUNK; icl++){
      const int wb = (cc*IC_CHUNK + icl)*9;
      #pragma unroll
      for (int ky = 0; ky < 3; ky++){
        #pragma unroll
        for (int kx = 0; kx < 3; kx++){
          float4 v  = s_in[icl][ry+ky][rx+kx];
          float4 wv = s_w [wb + ky*3 + kx];
          float  w4 = s_w4[wb + ky*3 + kx];
          a0 = fmaf(v.x, wv.x, a0);   // conv(x, W)
          s1 = fmaf(v.z, wv.y, s1);   // conv(x*q, 2W)
          s2 = fmaf(v.y, wv.z, s2);   // conv(q,   4W^2)
          s3 = fmaf(v.z, wv.w, s3);   // conv(x*q, 8W^3)
          s4 = fmaf(v.y, w4,   s4);   // conv(q,   16W^4)
        }
      }
    }
  }

  a0 += bias[oc];
  const float sg = 1.f / (1.f + expf(-a0));           // p0

  const int ho = rowbase + ry;
  const unsigned idx = ((b*OCC + oc)*HH + ho)*WW + rx;

  const float u  = jax_uniform(idx);
  const float nx = (u < sg) ? 1.0f : -1.0f;           // new_x

  // sigmoid derivatives
  const float d1  = sg*(1.f - sg);
  const float om2 = 1.f - 2.f*sg;
  const float d2  = d1*om2;
  const float d3  = d1*(1.f + 6.f*sg*(sg - 1.f));
  const float d4  = d2*(1.f + 12.f*sg*(sg - 1.f));

  const float dq = nx * (d1*s1 - 0.5f*d2*s2 + (1.f/6.f)*d3*s3 - (1.f/24.f)*d4*s4);

  out[idx]        = nx;     // new_x
  out[NPIX + idx] = dq;     // new_q (delta_0 is identically zero)
}

// ---------------- launch ----------------
extern "C" void kernel_launch(void* const* d_in, const int* in_sizes, int n_in,
                              void* d_out, int out_size){
  const float* x      = (const float*)d_in[0];
  const float* q      = (const float*)d_in[1];
  const float* weight = (const float*)d_in[2];
  const float* bias   = (const float*)d_in[3];
  float* out = (float*)d_out;

  prep_weights<<<(OCC*IC*9 + 255)/256, 256>>>(weight);
  prep_inputs<<<(BB*IC*HP*WP + 255)/256, 256>>>(x, q);
  dim3 grid(HH/8, OCC, BB);
  dim3 block(32, 8);
  sbc_main<<<grid, block>>>(bias, out);
}

// round 3
// speedup vs baseline: 2.2733x; 2.2733x over previous
#include <cuda_runtime.h>
#include <stdint.h>

#define BB 4
#define IC 64
#define OCC 64
#define HH 32
#define WW 32
#define HP 34
#define WP 34
#define NPIX (BB*OCC*HH*WW)   // 262144
#define ICC 2                 // ic per smem chunk

// ---------------- threefry-2x32-20, key = (0, 42) ----------------
__device__ __forceinline__ unsigned rotl32(unsigned v, int s){ return (v<<s)|(v>>(32-s)); }

__device__ __forceinline__ void threefry_0_42(unsigned x0, unsigned x1, unsigned &o0, unsigned &o1){
  const unsigned k0 = 0u, k1 = 42u, k2 = 0u ^ 42u ^ 0x1BD11BDAu;
  x0 += k0; x1 += k1;
  x0+=x1; x1=rotl32(x1,13); x1^=x0;
  x0+=x1; x1=rotl32(x1,15); x1^=x0;
  x0+=x1; x1=rotl32(x1,26); x1^=x0;
  x0+=x1; x1=rotl32(x1, 6); x1^=x0;
  x0+=k1; x1+=k2+1u;
  x0+=x1; x1=rotl32(x1,17); x1^=x0;
  x0+=x1; x1=rotl32(x1,29); x1^=x0;
  x0+=x1; x1=rotl32(x1,16); x1^=x0;
  x0+=x1; x1=rotl32(x1,24); x1^=x0;
  x0+=k2; x1+=k0+2u;
  x0+=x1; x1=rotl32(x1,13); x1^=x0;
  x0+=x1; x1=rotl32(x1,15); x1^=x0;
  x0+=x1; x1=rotl32(x1,26); x1^=x0;
  x0+=x1; x1=rotl32(x1, 6); x1^=x0;
  x0+=k0; x1+=k1+3u;
  x0+=x1; x1=rotl32(x1,17); x1^=x0;
  x0+=x1; x1=rotl32(x1,29); x1^=x0;
  x0+=x1; x1=rotl32(x1,16); x1^=x0;
  x0+=x1; x1=rotl32(x1,24); x1^=x0;
  x0+=k1; x1+=k2+4u;
  x0+=x1; x1=rotl32(x1,13); x1^=x0;
  x0+=x1; x1=rotl32(x1,15); x1^=x0;
  x0+=x1; x1=rotl32(x1,26); x1^=x0;
  x0+=x1; x1=rotl32(x1, 6); x1^=x0;
  x0+=k2; x1+=k0+5u;
  o0 = x0; o1 = x1;
}

// JAX partitionable threefry: counter (0, i); bits = o0 ^ o1.
__device__ __forceinline__ float jax_uniform(unsigned idx){
  unsigned r0, r1;
  threefry_0_42(0u, idx, r0, r1);
  unsigned bits = r0 ^ r1;
  return __uint_as_float((bits >> 9) | 0x3f800000u) - 1.0f;
}

// ---------------- fully fused kernel ----------------
// block: 32x8 = 256 threads; each thread computes 4 output rows (RY=4)
// -> block covers the full 32x32 image for one (b, oc).
// grid: (OC, B) = 256 blocks.
__global__ void __launch_bounds__(256, 2)
sbc_fused(const float* __restrict__ x, const float* __restrict__ q,
          const float* __restrict__ weight, const float* __restrict__ bias,
          float* __restrict__ out){
  __shared__ float4 s_in[ICC][HP][WP];   // padded {x, q, x*q, 0}: 36992 B
  __shared__ float4 s_w [IC*9];          // {w, 2w, 4w^2, 8w^3}:    9216 B
  __shared__ float  s_w4[IC*9];          // 16 w^4:                 2304 B

  const int oc = blockIdx.x;
  const int b  = blockIdx.y;
  const int rx = threadIdx.x;            // output col 0..31
  const int ry = threadIdx.y;            // 0..7
  const int r0 = ry * 4;                 // first output row of this thread
  const int tid = ry*32 + rx;

  // ---- per-block weight prep (oc-specific) ----
  for (int i = tid; i < IC*9; i += 256){
    float w  = weight[oc*IC*9 + i];
    float w2 = w*w;
    s_w [i] = make_float4(w, 2.f*w, 4.f*w2, 8.f*w2*w);
    s_w4[i] = 16.f*w2*w2;
  }

  // accumulators: [output row][{a0,s1,s2,s3,s4}]
  float a0[4] = {0,0,0,0};
  float s1[4] = {0,0,0,0};
  float s2[4] = {0,0,0,0};
  float s3[4] = {0,0,0,0};
  float s4[4] = {0,0,0,0};

  for (int cc = 0; cc < IC/ICC; cc++){
    __syncthreads();
    // load padded chunk (ICC channels x 34 x 34) directly from global x, q
    for (int i = tid; i < ICC*HP*WP; i += 256){
      int xw = i % WP; int t = i / WP;
      int yh = t % HP; int icl = t / HP;
      float4 v = make_float4(0.f, 0.f, 0.f, 0.f);
      if (xw >= 1 && xw <= WW && yh >= 1 && yh <= HH){
        int src = (((b*IC + cc*ICC + icl)*HH) + (yh-1))*WW + (xw-1);
        float xv = x[src], qv = q[src];
        v = make_float4(xv, qv, xv*qv, 0.f);
      }
      s_in[icl][yh][xw] = v;
    }
    __syncthreads();

    #pragma unroll
    for (int icl = 0; icl < ICC; icl++){
      const int wb = (cc*ICC + icl)*9;
      // hold this channel's 45 weight coefficients in registers
      float4 rw[9]; float rw4[9];
      #pragma unroll
      for (int j = 0; j < 9; j++){ rw[j] = s_w[wb+j]; rw4[j] = s_w4[wb+j]; }

      #pragma unroll
      for (int t = 0; t < 6; t++){
        float4 v0 = s_in[icl][r0+t][rx  ];
        float4 v1 = s_in[icl][r0+t][rx+1];
        float4 v2 = s_in[icl][r0+t][rx+2];
        #pragma unroll
        for (int ky = 0; ky < 3; ky++){
          const int o = t - ky;
          if (o >= 0 && o < 4){
            // kx = 0,1,2 ascending; 5 sums per tap (same order as R2 kernel)
            {
              float4 wv = rw[ky*3+0]; float w4 = rw4[ky*3+0];
              a0[o] = fmaf(v0.x, wv.x, a0[o]);
              s1[o] = fmaf(v0.z, wv.y, s1[o]);
              s2[o] = fmaf(v0.y, wv.z, s2[o]);
              s3[o] = fmaf(v0.z, wv.w, s3[o]);
              s4[o] = fmaf(v0.y, w4,   s4[o]);
            }
            {
              float4 wv = rw[ky*3+1]; float w4 = rw4[ky*3+1];
              a0[o] = fmaf(v1.x, wv.x, a0[o]);
              s1[o] = fmaf(v1.z, wv.y, s1[o]);
              s2[o] = fmaf(v1.y, wv.z, s2[o]);
              s3[o] = fmaf(v1.z, wv.w, s3[o]);
              s4[o] = fmaf(v1.y, w4,   s4[o]);
            }
            {
              float4 wv = rw[ky*3+2]; float w4 = rw4[ky*3+2];
              a0[o] = fmaf(v2.x, wv.x, a0[o]);
              s1[o] = fmaf(v2.z, wv.y, s1[o]);
              s2[o] = fmaf(v2.y, wv.z, s2[o]);
              s3[o] = fmaf(v2.z, wv.w, s3[o]);
              s4[o] = fmaf(v2.y, w4,   s4[o]);
            }
          }
        }
      }
    }
  }

  // ---- epilogue (identical math/order to the passing R2 kernel) ----
  const float bv = bias[oc];
  #pragma unroll
  for (int o = 0; o < 4; o++){
    const float a  = a0[o] + bv;
    const float sg = 1.f / (1.f + expf(-a));          // p0

    const int h = r0 + o;
    const unsigned idx = ((b*OCC + oc)*HH + h)*WW + rx;

    const float u  = jax_uniform(idx);
    const float nx = (u < sg) ? 1.0f : -1.0f;         // new_x

    const float d1  = sg*(1.f - sg);
    const float om2 = 1.f - 2.f*sg;
    const float d2  = d1*om2;
    const float d3  = d1*(1.f + 6.f*sg*(sg - 1.f));
    const float d4  = d2*(1.f + 12.f*sg*(sg - 1.f));

    const float dq = nx * (d1*s1[o] - 0.5f*d2*s2[o]
                         + (1.f/6.f)*d3*s3[o] - (1.f/24.f)*d4*s4[o]);

    out[idx]        = nx;
    out[NPIX + idx] = dq;
  }
}

// ---------------- launch ----------------
extern "C" void kernel_launch(void* const* d_in, const int* in_sizes, int n_in,
                              void* d_out, int out_size){
  const float* x      = (const float*)d_in[0];
  const float* q      = (const float*)d_in[1];
  const float* weight = (const float*)d_in[2];
  const float* bias   = (const float*)d_in[3];
  float* out = (float*)d_out;

  dim3 grid(OCC, BB);
  dim3 block(32, 8);
  sbc_fused<<<grid, block>>>(x, q, weight, bias, out);
}